// round 13
// baseline (speedup 1.0000x reference)
#include <cuda_runtime.h>

typedef unsigned long long u64;

#define EMAX      800000
#define NA_MAX    1024

// ---------------- device scratch (no allocations allowed) ----------------
__device__ int   g_cnt;
__device__ int   g_es[EMAX];
__device__ int   g_er[EMAX];
__device__ float g_aggr[NA_MAX * 128];

// ---------------- packed f32x2 helpers (FFMA2 path) ----------------
__device__ __forceinline__ u64 pk2(float v) {
    u64 r; asm("mov.b64 %0, {%1, %1};" : "=l"(r) : "f"(v)); return r;
}
__device__ __forceinline__ void fma2(u64& d, u64 a, u64 b) {
    asm("fma.rn.f32x2 %0, %1, %2, %0;" : "+l"(d) : "l"(a), "l"(b));
}
__device__ __forceinline__ float2 up2(u64 a) {
    float2 r; asm("mov.b64 {%0, %1}, %2;" : "=f"(r.x), "=f"(r.y) : "l"(a)); return r;
}

// ---------------- init: zero counter + aggr ----------------
__global__ void k_zero() {
    int i = blockIdx.x * blockDim.x + threadIdx.x;
    if (i == 0) g_cnt = 0;
    for (; i < NA_MAX * 128; i += gridDim.x * blockDim.x) g_aggr[i] = 0.f;
}

// ---------------- filter: compact edges with receiver < n_agents ----------------
__global__ void k_filter(const int* __restrict__ senders,
                         const int* __restrict__ receivers, int E, int nA) {
    int i = blockIdx.x * blockDim.x + threadIdx.x;
    for (; i < E; i += gridDim.x * blockDim.x) {
        int r = receivers[i];
        if (r < nA) {
            int p = atomicAdd(&g_cnt, 1);
            g_es[p] = senders[i];
            g_er[p] = r;
        }
    }
}

// ---------------- edge MLP: 32-edge tile, 3 fused GEMMs ----------------
// Activation SMEM layout: packed edge-pairs: float2 buf[pair][k]
// sIN  : float, pair row stride RINF floats (=RINF/2 u64)
// sH1/2: float2[16][256]

#define RINF 260
#define SMEM_EDGE (16*RINF*4 + 16*256*8*2 + 64*4)

// relu((in @ W[Kx256]) + b) -> out[16][256]; thread: 4 pairs x 4 cols
template<int K>
__device__ __forceinline__ void gemm_to256(const u64* __restrict__ in, int inStrideU64,
                                           const float* __restrict__ W,
                                           const float* __restrict__ bias,
                                           float2* __restrict__ out, int tid) {
    int eg = tid >> 6, colg = tid & 63;
    u64 acc[4][4];
#pragma unroll
    for (int j = 0; j < 4; j++)
#pragma unroll
        for (int i = 0; i < 4; i++) acc[j][i] = 0ull;

    const u64* ip0 = in + (4 * eg + 0) * inStrideU64;
    const u64* ip1 = in + (4 * eg + 1) * inStrideU64;
    const u64* ip2 = in + (4 * eg + 2) * inStrideU64;
    const u64* ip3 = in + (4 * eg + 3) * inStrideU64;
    const float* wr = W + colg;
#pragma unroll 4
    for (int k = 0; k < K; k++) {
        u64 a0 = ip0[k], a1 = ip1[k], a2 = ip2[k], a3 = ip3[k];
        u64 w0 = pk2(__ldg(wr)), w1 = pk2(__ldg(wr + 64));
        u64 w2 = pk2(__ldg(wr + 128)), w3 = pk2(__ldg(wr + 192));
        wr += 256;
        fma2(acc[0][0], a0, w0); fma2(acc[0][1], a0, w1); fma2(acc[0][2], a0, w2); fma2(acc[0][3], a0, w3);
        fma2(acc[1][0], a1, w0); fma2(acc[1][1], a1, w1); fma2(acc[1][2], a1, w2); fma2(acc[1][3], a1, w3);
        fma2(acc[2][0], a2, w0); fma2(acc[2][1], a2, w1); fma2(acc[2][2], a2, w2); fma2(acc[2][3], a2, w3);
        fma2(acc[3][0], a3, w0); fma2(acc[3][1], a3, w1); fma2(acc[3][2], a3, w2); fma2(acc[3][3], a3, w3);
    }
#pragma unroll
    for (int i = 0; i < 4; i++) {
        float b = __ldg(bias + colg + 64 * i);
#pragma unroll
        for (int j = 0; j < 4; j++) {
            float2 v = up2(acc[j][i]);
            v.x = fmaxf(v.x + b, 0.f);
            v.y = fmaxf(v.y + b, 0.f);
            out[(4 * eg + j) * 256 + colg + 64 * i] = v;
        }
    }
}

__global__ void __launch_bounds__(256, 2)
k_edge(const float* __restrict__ x,
       const float* __restrict__ Wm1, const float* __restrict__ bm1,
       const float* __restrict__ Wm2, const float* __restrict__ bm2,
       const float* __restrict__ Wm3, const float* __restrict__ bm3) {
    extern __shared__ __align__(16) unsigned char smem[];
    float*  sIN = (float*)smem;
    float2* sH1 = (float2*)(smem + 16 * RINF * 4);
    float2* sH2 = (float2*)(smem + 16 * RINF * 4 + 16 * 256 * 8);
    int*    sS  = (int*)(smem + 16 * RINF * 4 + 16 * 256 * 8 * 2);
    int*    sR  = sS + 32;

    int tid = threadIdx.x;
    int Ec  = g_cnt;
    int nT  = (Ec + 31) >> 5;

    for (int t = blockIdx.x; t < nT; t += gridDim.x) {
        int base = t << 5;
        if (tid < 32) {
            int gi = base + tid;
            sS[tid] = (gi < Ec) ? g_es[gi] : 0;
            sR[tid] = (gi < Ec) ? g_er[gi] : 0;
        }
        __syncthreads();
        // gather concat(x[s], x[r]) into packed-pair layout
#pragma unroll
        for (int idx = tid; idx < 32 * 128; idx += 256) {
            int e = idx & 31, k = idx >> 5;
            float v = 0.f;
            if (base + e < Ec) {
                int node = (k < 64) ? sS[e] : sR[e];
                v = __ldg(x + node * 64 + (k & 63));
            }
            sIN[(e >> 1) * RINF + 2 * k + (e & 1)] = v;
        }
        __syncthreads();
        gemm_to256<128>((const u64*)sIN, RINF / 2, Wm1, bm1, sH1, tid);
        __syncthreads();
        gemm_to256<256>((const u64*)sH1, 256, Wm2, bm2, sH2, tid);
        __syncthreads();
        // GEMM3: [32,256] @ [256,128] + bias -> scatter-add to aggr
        {
            int eg = tid >> 5, colg = tid & 31;   // eg 0..7: 2 pairs each
            u64 acc[2][4];
#pragma unroll
            for (int j = 0; j < 2; j++)
#pragma unroll
                for (int i = 0; i < 4; i++) acc[j][i] = 0ull;
            const u64* ipA = (const u64*)sH2 + (2 * eg) * 256;
            const u64* ipB = ipA + 256;
            const float* wr = Wm3 + colg;
#pragma unroll 4
            for (int k = 0; k < 256; k++) {
                u64 a0 = ipA[k], a1 = ipB[k];
                u64 w0 = pk2(__ldg(wr)), w1 = pk2(__ldg(wr + 32));
                u64 w2 = pk2(__ldg(wr + 64)), w3 = pk2(__ldg(wr + 96));
                wr += 128;
                fma2(acc[0][0], a0, w0); fma2(acc[0][1], a0, w1); fma2(acc[0][2], a0, w2); fma2(acc[0][3], a0, w3);
                fma2(acc[1][0], a1, w0); fma2(acc[1][1], a1, w1); fma2(acc[1][2], a1, w2); fma2(acc[1][3], a1, w3);
            }
#pragma unroll
            for (int i = 0; i < 4; i++) {
                int c = colg + 32 * i;
                float b = __ldg(bm3 + c);
#pragma unroll
                for (int j = 0; j < 2; j++) {
                    int p = 2 * eg + j;
                    float2 v = up2(acc[j][i]);
                    int e0 = 2 * p, e1 = 2 * p + 1;
                    if (base + e0 < Ec) atomicAdd(&g_aggr[sR[e0] * 128 + c], v.x + b);
                    if (base + e1 < Ec) atomicAdd(&g_aggr[sR[e1] * 128 + c], v.y + b);
                }
            }
        }
        __syncthreads();
    }
}

// ---------------- node + critic chain: 8 agents per block ----------------
// thread: 1 pair (eg = tid>>6) x N/64 cols; buffers float2[4][256]
template<int K, int N, bool RELU>
__device__ __forceinline__ void tile_gemm(const float2* __restrict__ inb,
                                          const float* __restrict__ W,
                                          const float* __restrict__ bias,
                                          float2* __restrict__ outb, int tid) {
    int eg = tid >> 6, colg = tid & 63;
    constexpr int NI = N / 64;
    u64 acc[NI];
#pragma unroll
    for (int i = 0; i < NI; i++) acc[i] = 0ull;
    const u64* ip = (const u64*)inb + eg * 256;
    const float* wr = W + colg;
#pragma unroll 4
    for (int k = 0; k < K; k++) {
        u64 a = ip[k];
#pragma unroll
        for (int i = 0; i < NI; i++) {
            u64 w = pk2(__ldg(wr + 64 * i));
            fma2(acc[i], a, w);
        }
        wr += N;
    }
#pragma unroll
    for (int i = 0; i < NI; i++) {
        int c = colg + 64 * i;
        float b = __ldg(bias + c);
        float2 v = up2(acc[i]);
        v.x += b; v.y += b;
        if (RELU) { v.x = fmaxf(v.x, 0.f); v.y = fmaxf(v.y, 0.f); }
        outb[eg * 256 + c] = v;
    }
}

__global__ void __launch_bounds__(256)
k_node(const float* __restrict__ x, const float* __restrict__ actions,
       float* __restrict__ out,
       const float* Wa1, const float* ba1, const float* Wa2, const float* ba2,
       const float* Wa3, const float* ba3,
       const float* Wu1, const float* bu1, const float* Wu2, const float* bu2,
       const float* Wu3, const float* bu3,
       const float* Wact, const float* bact,
       const float* Wh1, const float* bh1, const float* Wh2, const float* bh2,
       const float* Wq,  const float* bq) {
    __shared__ __align__(16) float2 A[4 * 256];
    __shared__ __align__(16) float2 B[4 * 256];
    float* Af = (float*)A;
    float* Bf = (float*)B;
    int tid = threadIdx.x;
    int a0  = blockIdx.x * 8;

    // load aggregated messages for 8 agents
#pragma unroll
    for (int idx = tid; idx < 8 * 128; idx += 256) {
        int e = idx & 7, k = idx >> 3;
        Af[(e >> 1) * 512 + 2 * k + (e & 1)] = g_aggr[(a0 + e) * 128 + k];
    }
    __syncthreads();
    tile_gemm<128, 128, true >(A, Wa1, ba1, B, tid); __syncthreads();
    tile_gemm<128, 128, true >(B, Wa2, ba2, A, tid); __syncthreads();
    tile_gemm<128, 128, false>(A, Wa3, ba3, B, tid); __syncthreads();
    // u = concat(x, a)
    for (int idx = tid; idx < 8 * 192; idx += 256) {
        int e = idx & 7, k = idx >> 3;
        float v = (k < 64) ? __ldg(x + (a0 + e) * 64 + k)
                           : Bf[(e >> 1) * 512 + 2 * (k - 64) + (e & 1)];
        Af[(e >> 1) * 512 + 2 * k + (e & 1)] = v;
    }
    __syncthreads();
    tile_gemm<192, 256, true >(A, Wu1, bu1, B, tid); __syncthreads();
    tile_gemm<256, 256, true >(B, Wu2, bu2, A, tid); __syncthreads();
    tile_gemm<256, 128, false>(A, Wu3, bu3, B, tid); __syncthreads();
    // z = concat(feats, relu(actions @ W_act + b_act))
    for (int idx = tid; idx < 8 * 256; idx += 256) {
        int e = idx & 7, k = idx >> 3;
        float v;
        if (k < 128) {
            v = Bf[(e >> 1) * 512 + 2 * k + (e & 1)];
        } else {
            int c = k - 128;
            float s = __ldg(bact + c);
            const float* ar = actions + (a0 + e) * 16;
#pragma unroll
            for (int t2 = 0; t2 < 16; t2++)
                s = fmaf(__ldg(ar + t2), __ldg(Wact + t2 * 128 + c), s);
            v = fmaxf(s, 0.f);
        }
        Af[(e >> 1) * 512 + 2 * k + (e & 1)] = v;
    }
    __syncthreads();
    tile_gemm<256, 256, true>(A, Wh1, bh1, B, tid); __syncthreads();
    tile_gemm<256, 256, true>(B, Wh2, bh2, A, tid); __syncthreads();
    // q = z @ W_q + b_q  (one warp per agent row)
    int w = tid >> 5, lane = tid & 31;
    int e = w;
    float s = 0.f;
    for (int k = lane; k < 256; k += 32)
        s = fmaf(Af[(e >> 1) * 512 + 2 * k + (e & 1)], __ldg(Wq + k), s);
#pragma unroll
    for (int o = 16; o; o >>= 1) s += __shfl_xor_sync(0xffffffffu, s, o);
    if (lane == 0) out[a0 + e] = s + __ldg(bq);
}

// ---------------- launch ----------------
extern "C" void kernel_launch(void* const* d_in, const int* in_sizes, int n_in,
                              void* d_out, int out_size) {
    const float* x         = (const float*)d_in[0];
    const float* actions   = (const float*)d_in[1];
    const int*   senders   = (const int*)d_in[2];
    const int*   receivers = (const int*)d_in[3];
    // n_agents scalar may or may not be materialized as input 4
    int wo = (in_sizes[4] == 1) ? 5 : 4;
    const float* Wm1 = (const float*)d_in[wo + 0],  *bm1 = (const float*)d_in[wo + 1];
    const float* Wm2 = (const float*)d_in[wo + 2],  *bm2 = (const float*)d_in[wo + 3];
    const float* Wm3 = (const float*)d_in[wo + 4],  *bm3 = (const float*)d_in[wo + 5];
    const float* Wa1 = (const float*)d_in[wo + 6],  *ba1 = (const float*)d_in[wo + 7];
    const float* Wa2 = (const float*)d_in[wo + 8],  *ba2 = (const float*)d_in[wo + 9];
    const float* Wa3 = (const float*)d_in[wo + 10], *ba3 = (const float*)d_in[wo + 11];
    const float* Wu1 = (const float*)d_in[wo + 12], *bu1 = (const float*)d_in[wo + 13];
    const float* Wu2 = (const float*)d_in[wo + 14], *bu2 = (const float*)d_in[wo + 15];
    const float* Wu3 = (const float*)d_in[wo + 16], *bu3 = (const float*)d_in[wo + 17];
    const float* Wact= (const float*)d_in[wo + 18], *bact= (const float*)d_in[wo + 19];
    const float* Wh1 = (const float*)d_in[wo + 20], *bh1 = (const float*)d_in[wo + 21];
    const float* Wh2 = (const float*)d_in[wo + 22], *bh2 = (const float*)d_in[wo + 23];
    const float* Wq  = (const float*)d_in[wo + 24], *bq  = (const float*)d_in[wo + 25];

    int E  = in_sizes[3];
    int nA = in_sizes[1] / 16;   // 1024

    cudaFuncSetAttribute(k_edge, cudaFuncAttributeMaxDynamicSharedMemorySize, SMEM_EDGE);

    k_zero<<<512, 256>>>();
    k_filter<<<(E + 255) / 256, 256>>>(senders, receivers, E, nA);
    k_edge<<<296, 256, SMEM_EDGE>>>(x, Wm1, bm1, Wm2, bm2, Wm3, bm3);
    k_node<<<nA / 8, 256>>>(x, actions, (float*)d_out,
                            Wa1, ba1, Wa2, ba2, Wa3, ba3,
                            Wu1, bu1, Wu2, bu2, Wu3, bu3,
                            Wact, bact, Wh1, bh1, Wh2, bh2, Wq, bq);
}